// round 16
// baseline (speedup 1.0000x reference)
#include <cuda_runtime.h>
#include <cuda_bf16.h>
#include <cstdint>

#define BB 16
#define CC 64
#define NN 4096   // H*W
#define MM 1024   // N/4

// Scratch (allocation-free: __device__ globals)
__device__ __align__(16) float g_theta[BB * NN * 8];              // [b][q][8]
__device__ __align__(16) float g_phi[BB * MM * 8];                // [b][m][8]
__device__ __align__(16) __nv_bfloat16 g_gbf[BB * 32 * MM];       // [b][c'][m] bf16

typedef unsigned long long ull;

__device__ __forceinline__ ull fma2(ull a, ull b, ull c) {
    ull d;
    asm("fma.rn.f32x2 %0, %1, %2, %3;" : "=l"(d) : "l"(a), "l"(b), "l"(c));
    return d;
}
__device__ __forceinline__ ull add2(ull a, ull b) {
    ull d;
    asm("add.rn.f32x2 %0, %1, %2;" : "=l"(d) : "l"(a), "l"(b));
    return d;
}
__device__ __forceinline__ ull pack2(float lo, float hi) {
    ull d;
    asm("mov.b64 %0, {%1, %2};" : "=l"(d) : "f"(lo), "f"(hi));
    return d;
}
__device__ __forceinline__ ull packu(uint32_t lo, uint32_t hi) {
    ull d;
    asm("mov.b64 %0, {%1, %2};" : "=l"(d) : "r"(lo), "r"(hi));
    return d;
}
__device__ __forceinline__ void unpack2(ull v, float& lo, float& hi) {
    asm("mov.b64 {%0, %1}, %2;" : "=f"(lo), "=f"(hi) : "l"(v));
}
__device__ __forceinline__ void u64lohi(ull v, uint32_t& lo, uint32_t& hi) {
    asm("mov.b64 {%0, %1}, %2;" : "=r"(lo), "=r"(hi) : "l"(v));
}
__device__ __forceinline__ uint32_t cvt_tf32(float f) {
    uint32_t r;
    asm("cvt.rna.tf32.f32 %0, %1;" : "=r"(r) : "f"(f));
    return r;
}
__device__ __forceinline__ float ex2f(float x) {
    float r;
    asm("ex2.approx.f32 %0, %1;" : "=f"(r) : "f"(x));
    return r;
}
// returns {lo, hi} packed bf16x2 (PTX: first operand -> high half)
__device__ __forceinline__ uint32_t bf16pk(float hi, float lo) {
    uint32_t r;
    asm("cvt.rn.bf16x2.f32 %0, %1, %2;" : "=r"(r) : "f"(hi), "f"(lo));
    return r;
}
__device__ __forceinline__ void mma_tf32(float& d0, float& d1, float& d2, float& d3,
        uint32_t a0, uint32_t a1, uint32_t a2, uint32_t a3,
        uint32_t b0, uint32_t b1) {
    asm("mma.sync.aligned.m16n8k8.row.col.f32.tf32.tf32.f32 "
        "{%0,%1,%2,%3}, {%4,%5,%6,%7}, {%8,%9}, {%10,%11,%12,%13};"
        : "=f"(d0), "=f"(d1), "=f"(d2), "=f"(d3)
        : "r"(a0), "r"(a1), "r"(a2), "r"(a3), "r"(b0), "r"(b1),
          "f"(0.0f), "f"(0.0f), "f"(0.0f), "f"(0.0f));
}
__device__ __forceinline__ void mma_bf16(float* d,
        uint32_t a0, uint32_t a1, uint32_t a2, uint32_t a3,
        uint32_t b0, uint32_t b1) {
    asm("mma.sync.aligned.m16n8k16.row.col.f32.bf16.bf16.f32 "
        "{%0,%1,%2,%3}, {%4,%5,%6,%7}, {%8,%9}, {%0,%1,%2,%3};"
        : "+f"(d[0]), "+f"(d[1]), "+f"(d[2]), "+f"(d[3])
        : "r"(a0), "r"(a1), "r"(a2), "r"(a3), "r"(b0), "r"(b1));
}
// packed exp2 via magic rounding + deg-4 poly + exponent splice.
// in: t2 = packed (t0,t1); out: float BITS of (2^t0, 2^t1).
__device__ __forceinline__ void exp2pk(ull t2,
        ull M, ull NM, ull NONE, ull C4, ull C3, ull C2, ull C1, ull ONE,
        uint32_t& lo, uint32_t& hi) {
    ull z = add2(t2, M);                 // round-to-nearest int in mantissa
    ull zm = add2(z, NM);                // n as float (exact)
    ull f = fma2(zm, NONE, t2);          // f = t - n, in [-0.5, 0.5]
    ull p = fma2(f, C4, C3);
    p = fma2(f, p, C2);
    p = fma2(f, p, C1);
    p = fma2(f, p, ONE);
    uint32_t zl, zh, pl, ph;
    u64lohi(z, zl, zh);
    u64lohi(p, pl, ph);
    lo = pl + (zl << 23);                // bits(z)<<23 == n<<23 exactly
    hi = ph + (zh << 23);
}

// SMEM layout (attn):
//   phi_p: [1024 rows][32B]  row m, slot t (0-3): u64 {tf32 phi[m][t], tf32 phi[m][t+4]}
//   g_p:   [32 rows][2080B]  pitch ≡32 (mod 128) -> conflict-free LDS.64 phases
#define SO_G      32768
#define G_PITCH   2080
#define G_NT      (8 * G_PITCH)                 // 16640: 8 rows per channel tile
#define SO_WO     (SO_G + 32 * G_PITCH)         // 99328; 64 rows x 72B
#define SO_BIAS   (SO_WO + 64 * 72)             // 103936; 64 floats
#define SM_ATTN   (SO_BIAS + 256)               // 104192

// ---------------------------------------------------------------------------
// Kernel 1: fused theta/phi/g. TWO threads per (window, position), each
//   covering 32 channels; packed shfl-add recombine (xor 4), then
//   maxpool reduce over the quad (xor 1, xor 2).
// ---------------------------------------------------------------------------
__global__ void __launch_bounds__(256) pre_kernel(
        const float* __restrict__ x,
        const float* __restrict__ Wt, const float* __restrict__ bt,
        const float* __restrict__ Wp, const float* __restrict__ bp,
        const float* __restrict__ Wg, const float* __restrict__ bg) {
    __shared__ __align__(16) float WT[64 * 48];  // [c][o]: 0-7 th, 8-15 phi, 16-47 g
    __shared__ float b_s[48];
    int tid = threadIdx.x;
    for (int i = tid; i < 3072; i += 256) {
        int o = i % 48, c = i / 48;
        WT[i] = (o < 8) ? Wt[o * 64 + c]
              : (o < 16) ? Wp[(o - 8) * 64 + c]
                         : Wg[(o - 16) * 64 + c];
    }
    if (tid < 48) b_s[tid] = (tid < 8) ? bt[tid]
                           : (tid < 16) ? bp[tid - 8] : bg[tid - 16];
    __syncthreads();

    int lane = tid & 31;
    int idx = blockIdx.x * 256 + tid;
    int pm = idx >> 3;          // pooled pixel
    int half = (idx >> 2) & 1;  // channel half
    int pos = idx & 3;          // window position
    int b = pm >> 10;
    int m = pm & 1023;
    int hp = m >> 5, wp = m & 31;
    int q = (2 * hp + (pos >> 1)) * 64 + 2 * wp + (pos & 1);
    int c0 = half * 32;
    const float* xb = x + ((size_t)b * CC + c0) * NN + q;
    const float* wbase = WT + c0 * 48;

    ull y[24];
    #pragma unroll
    for (int j = 0; j < 24; j++) y[j] = 0ull;
    #pragma unroll 8
    for (int c = 0; c < 32; c++) {
        float xv = xb[(size_t)c * NN];
        ull v2 = pack2(xv, xv);
        const ulonglong2* wr = (const ulonglong2*)(wbase + c * 48);
        #pragma unroll
        for (int j = 0; j < 12; j++) {
            ulonglong2 wv = wr[j];
            y[2 * j]     = fma2(v2, wv.x, y[2 * j]);
            y[2 * j + 1] = fma2(v2, wv.y, y[2 * j + 1]);
        }
    }
    // combine channel halves (packed adds across xor-4 lanes)
    #pragma unroll
    for (int j = 0; j < 24; j++)
        y[j] = add2(y[j], (ull)__shfl_xor_sync(0xffffffffu, y[j], 4));

    float v[48];
    #pragma unroll
    for (int j = 0; j < 24; j++) unpack2(y[j], v[2 * j], v[2 * j + 1]);

    // theta: one store per pixel (half==0 lanes)
    if (half == 0) {
        float4* op = (float4*)(g_theta + ((size_t)b * NN + q) * 8);
        op[0] = make_float4(v[0] + b_s[0], v[1] + b_s[1],
                            v[2] + b_s[2], v[3] + b_s[3]);
        op[1] = make_float4(v[4] + b_s[4], v[5] + b_s[5],
                            v[6] + b_s[6], v[7] + b_s[7]);
    }
    // phi/g: maxpool across the quad
    #pragma unroll
    for (int j = 8; j < 48; j++) {
        v[j] = fmaxf(v[j], __shfl_xor_sync(0xffffffffu, v[j], 1));
        v[j] = fmaxf(v[j], __shfl_xor_sync(0xffffffffu, v[j], 2));
    }
    if ((lane & 7) == 0) {      // pos==0 && half==0
        float* php = g_phi + (size_t)pm * 8;
        #pragma unroll
        for (int k = 0; k < 8; k++) php[k] = v[8 + k] + b_s[8 + k];
        __nv_bfloat16* gp = g_gbf + (size_t)b * 32 * MM + m;
        #pragma unroll
        for (int j = 0; j < 32; j++)
            gp[(size_t)j * MM] = __float2bfloat16(v[16 + j] + b_s[16 + j]);
    }
}

// ---------------------------------------------------------------------------
// Kernel 2: fused flash attention + output projection + residual.
//   Two 16-query groups per warp share key-chunk B fragments. Group A uses
//   MUFU ex2; group B uses a packed f32x2 polynomial exp2 on the FMA pipe
//   (halves MUFU pressure). Denominators accumulate packed.
// ---------------------------------------------------------------------------
__global__ void __launch_bounds__(256, 2) attn_kernel(
        const float* __restrict__ x,
        const float* __restrict__ Wo, const float* __restrict__ bo,
        const float* __restrict__ gam,
        float* __restrict__ out) {
    extern __shared__ __align__(16) char sm[];
    char* wo_s = sm + SO_WO;                   // 64 rows x 72B (bf16 pairs)
    float* b_s = (float*)(sm + SO_BIAS);       // 64 floats

    int tid = threadIdx.x;
    int b = blockIdx.x >> 4;
    int qt = blockIdx.x & 15;

    // Stage phi (packed tf32 pairs), g (packed bf16 u64 slots), W_o, bias
    {
        for (int m = tid; m < 1024; m += 256) {
            const float4* pr = (const float4*)(g_phi + ((size_t)b * MM + m) * 8);
            float4 f0 = pr[0], f1 = pr[1];
            uint2* dst = (uint2*)(sm + m * 32);
            dst[0] = make_uint2(cvt_tf32(f0.x), cvt_tf32(f1.x));
            dst[1] = make_uint2(cvt_tf32(f0.y), cvt_tf32(f1.y));
            dst[2] = make_uint2(cvt_tf32(f0.z), cvt_tf32(f1.z));
            dst[3] = make_uint2(cvt_tf32(f0.w), cvt_tf32(f1.w));
        }
        const uint32_t* gsrc = (const uint32_t*)(g_gbf + (size_t)b * 32 * MM);
        for (int i = tid; i < 8192; i += 256) {
            int r = i >> 8;            // 0..31
            int c = (i >> 2) & 63;     // chunk
            int t = i & 3;             // slot
            const uint32_t* src = gsrc + r * (MM / 2) + c * 8;
            *(uint2*)(sm + SO_G + r * G_PITCH + c * 32 + t * 8) =
                make_uint2(src[t], src[t + 4]);
        }
        for (int i = tid; i < 1024; i += 256) {        // W_o: [co][ci pair]
            int co = i >> 4, pr = i & 15;
            float lo = Wo[co * 32 + 2 * pr];
            float hi = Wo[co * 32 + 2 * pr + 1];
            *(uint32_t*)(wo_s + co * 72 + pr * 4) = bf16pk(hi, lo);
        }
        if (tid < 64) b_s[tid] = bo[tid];
    }
    __syncthreads();

    int w = tid >> 5, lane = tid & 31;
    int t4 = lane >> 2, tm4 = lane & 3;
    int q0 = qt * 256 + w * 16;            // group A queries
    int q1 = q0 + 128;                     // group B queries

    // theta A-fragments (tf32), pre-scaled by log2(e)
    const float L2E = 1.4426950408889634f;
    const float* tpA = g_theta + ((size_t)b * NN + q0) * 8;
    const float* tpB = g_theta + ((size_t)b * NN + q1) * 8;
    uint32_t taA0 = cvt_tf32(tpA[t4 * 8 + tm4] * L2E);
    uint32_t taA1 = cvt_tf32(tpA[(t4 + 8) * 8 + tm4] * L2E);
    uint32_t taA2 = cvt_tf32(tpA[t4 * 8 + tm4 + 4] * L2E);
    uint32_t taA3 = cvt_tf32(tpA[(t4 + 8) * 8 + tm4 + 4] * L2E);
    uint32_t taB0 = cvt_tf32(tpB[t4 * 8 + tm4] * L2E);
    uint32_t taB1 = cvt_tf32(tpB[(t4 + 8) * 8 + tm4] * L2E);
    uint32_t taB2 = cvt_tf32(tpB[t4 * 8 + tm4 + 4] * L2E);
    uint32_t taB3 = cvt_tf32(tpB[(t4 + 8) * 8 + tm4 + 4] * L2E);

    // packed-poly constants (warp-uniform; ptxas promotes to UR)
    const ull K_M   = pack2(12582912.0f, 12582912.0f);
    const ull K_NM  = pack2(-12582912.0f, -12582912.0f);
    const ull K_N1  = pack2(-1.0f, -1.0f);
    const ull K_C4  = pack2(0.00961804f, 0.00961804f);
    const ull K_C3  = pack2(0.05550411f, 0.05550411f);
    const ull K_C2  = pack2(0.24022650f, 0.24022650f);
    const ull K_C1  = pack2(0.69314718f, 0.69314718f);
    const ull K_ONE = pack2(1.0f, 1.0f);

    float oA[16], oB[16];
    #pragma unroll
    for (int j = 0; j < 16; j++) { oA[j] = 0.0f; oB[j] = 0.0f; }
    ull accAlo = 0ull, accAhi = 0ull, accBlo = 0ull, accBhi = 0ull;

    const char* pp = sm + t4 * 32 + tm4 * 8;                 // phi ptr, +512/chunk
    const char* gp = sm + SO_G + t4 * G_PITCH + tm4 * 8;     // g ptr,  +32/chunk

    #pragma unroll 2
    for (int ch = 0; ch < 64; ch++) {
        // B fragments: 6x LDS.64, zero address math
        ull vpb = *(const ull*)pp;
        ull vpc = *(const ull*)(pp + 256);
        ull vg0 = *(const ull*)gp;
        ull vg1 = *(const ull*)(gp + G_NT);
        ull vg2 = *(const ull*)(gp + 2 * G_NT);
        ull vg3 = *(const ull*)(gp + 3 * G_NT);
        pp += 512;
        gp += 32;

        uint32_t pb0, pb1, pc0, pc1;
        u64lohi(vpb, pb0, pb1);
        u64lohi(vpc, pc0, pc1);
        uint32_t gb0[4], gb1[4];
        u64lohi(vg0, gb0[0], gb1[0]);
        u64lohi(vg1, gb0[1], gb1[1]);
        u64lohi(vg2, gb0[2], gb1[2]);
        u64lohi(vg3, gb0[3], gb1[3]);

        // ---- group A: MUFU path ----
        float s0, s1, s2, s3, s4, s5, s6, s7;
        mma_tf32(s0, s1, s2, s3, taA0, taA1, taA2, taA3, pb0, pb1);
        mma_tf32(s4, s5, s6, s7, taA0, taA1, taA2, taA3, pc0, pc1);
        float a0 = ex2f(s0), a1 = ex2f(s1), a2 = ex2f(s2), a3 = ex2f(s3);
        float a4 = ex2f(s4), a5 = ex2f(s5), a6 = ex2f(s6), a7 = ex2f(s7);
        accAlo = add2(accAlo, pack2(a0, a1));
        accAlo = add2(accAlo, pack2(a4, a5));
        accAhi = add2(accAhi, pack2(a2, a3));
        accAhi = add2(accAhi, pack2(a6, a7));
        uint32_t paA0 = bf16pk(a1, a0);
        uint32_t paA1 = bf16pk(a3, a2);
        uint32_t paA2 = bf16pk(a5, a4);
        uint32_t paA3 = bf16pk(a7, a6);

        // ---- group B: packed FMA-pipe poly exp2 ----
        float u0, u1, u2, u3, u4, u5, u6, u7;
        mma_tf32(u0, u1, u2, u3, taB0, taB1, taB2, taB3, pb0, pb1);
        mma_tf32(u4, u5, u6, u7, taB0, taB1, taB2, taB3, pc0, pc1);
        uint32_t e0b, e1b, e2b, e3b, e4b, e5b, e6b, e7b;
        exp2pk(pack2(u0, u1), K_M, K_NM, K_N1, K_C4, K_C3, K_C2, K_C1, K_ONE, e0b, e1b);
        exp2pk(pack2(u2, u3), K_M, K_NM, K_N1, K_C4, K_C3, K_C2, K_C1, K_ONE, e2b, e3b);
        exp2pk(pack2(u4, u5), K_M, K_NM, K_N1, K_C4, K_C3, K_C2, K_C1, K_ONE, e4b, e5b);
        exp2pk(pack2(u6, u7), K_M, K_NM, K_N1, K_C4, K_C3, K_C2, K_C1, K_ONE, e6b, e7b);
        accBlo = add2(accBlo, packu(e0b, e1b));
        accBlo = add2(accBlo, packu(e4b, e5b));
        accBhi = add2(accBhi, packu(e2b, e3b));
        accBhi = add2(accBhi, packu(e6b, e7b));
        uint32_t paB0 = bf16pk(__uint_as_float(e1b), __uint_as_float(e0b));
        uint32_t paB1 = bf16pk(__uint_as_float(e3b), __uint_as_float(e2b));
        uint32_t paB2 = bf16pk(__uint_as_float(e5b), __uint_as_float(e4b));
        uint32_t paB3 = bf16pk(__uint_as_float(e7b), __uint_as_float(e6b));

        #pragma unroll
        for (int nt = 0; nt < 4; nt++) {
            mma_bf16(oA + nt * 4, paA0, paA1, paA2, paA3, gb0[nt], gb1[nt]);
            mma_bf16(oB + nt * 4, paB0, paB1, paB2, paB3, gb0[nt], gb1[nt]);
        }
    }

    float dl0, dl1, dh0, dh1;
    unpack2(accAlo, dl0, dl1);
    unpack2(accAhi, dh0, dh1);
    float denA_lo = dl0 + dl1, denA_hi = dh0 + dh1;
    unpack2(accBlo, dl0, dl1);
    unpack2(accBhi, dh0, dh1);
    float denB_lo = dl0 + dl1, denB_hi = dh0 + dh1;

    denA_lo += __shfl_xor_sync(0xffffffffu, denA_lo, 1);
    denA_lo += __shfl_xor_sync(0xffffffffu, denA_lo, 2);
    denA_hi += __shfl_xor_sync(0xffffffffu, denA_hi, 1);
    denA_hi += __shfl_xor_sync(0xffffffffu, denA_hi, 2);
    denB_lo += __shfl_xor_sync(0xffffffffu, denB_lo, 1);
    denB_lo += __shfl_xor_sync(0xffffffffu, denB_lo, 2);
    denB_hi += __shfl_xor_sync(0xffffffffu, denB_hi, 1);
    denB_hi += __shfl_xor_sync(0xffffffffu, denB_hi, 2);
    float ilA = 1.0f / denA_lo, ihA = 1.0f / denA_hi;
    float ilB = 1.0f / denB_lo, ihB = 1.0f / denB_hi;

    // ---- fused output projection + residual, both groups ----
    uint32_t paA[8], paB[8];
    #pragma unroll
    for (int h = 0; h < 4; h++) {
        paA[2 * h]     = bf16pk(oA[4 * h + 1] * ilA, oA[4 * h]     * ilA);
        paA[2 * h + 1] = bf16pk(oA[4 * h + 3] * ihA, oA[4 * h + 2] * ihA);
        paB[2 * h]     = bf16pk(oB[4 * h + 1] * ilB, oB[4 * h]     * ilB);
        paB[2 * h + 1] = bf16pk(oB[4 * h + 3] * ihB, oB[4 * h + 2] * ihB);
    }

    float gma = gam[0];
    const float* xb = x + (size_t)b * CC * NN;
    float* outb = out + (size_t)b * CC * NN;
    int qA_lo = q0 + t4, qA_hi = qA_lo + 8;
    int qB_lo = q1 + t4, qB_hi = qB_lo + 8;

    #pragma unroll
    for (int ntc = 0; ntc < 8; ntc++) {
        const char* wb = wo_s + (ntc * 8 + t4) * 72 + tm4 * 4;
        uint32_t w0 = *(const uint32_t*)wb;
        uint32_t w1 = *(const uint32_t*)(wb + 16);
        uint32_t w2 = *(const uint32_t*)(wb + 32);
        uint32_t w3 = *(const uint32_t*)(wb + 48);
        int co = ntc * 8 + 2 * tm4;
        size_t r0 = (size_t)co * NN, r1 = (size_t)(co + 1) * NN;
        float bc0 = b_s[co], bc1 = b_s[co + 1];

        float accA[4] = {0.0f, 0.0f, 0.0f, 0.0f};
        mma_bf16(accA, paA[0], paA[1], paA[2], paA[3], w0, w1);
        mma_bf16(accA, paA[4], paA[5], paA[6], paA[7], w2, w3);
        outb[r0 + qA_lo] = gma * (accA[0] + bc0) + xb[r0 + qA_lo];
        outb[r1 + qA_lo] = gma * (accA[1] + bc1) + xb[r1 + qA_lo];
        outb[r0 + qA_hi] = gma * (accA[2] + bc0) + xb[r0 + qA_hi];
        outb[r1 + qA_hi] = gma * (accA[3] + bc1) + xb[r1 + qA_hi];

        float accB[4] = {0.0f, 0.0f, 0.0f, 0.0f};
        mma_bf16(accB, paB[0], paB[1], paB[2], paB[3], w0, w1);
        mma_bf16(accB, paB[4], paB[5], paB[6], paB[7], w2, w3);
        outb[r0 + qB_lo] = gma * (accB[0] + bc0) + xb[r0 + qB_lo];
        outb[r1 + qB_lo] = gma * (accB[1] + bc1) + xb[r1 + qB_lo];
        outb[r0 + qB_hi] = gma * (accB[2] + bc0) + xb[r0 + qB_hi];
        outb[r1 + qB_hi] = gma * (accB[3] + bc1) + xb[r1 + qB_hi];
    }
}

// ---------------------------------------------------------------------------
extern "C" void kernel_launch(void* const* d_in, const int* in_sizes, int n_in,
                              void* d_out, int out_size) {
    const float* x   = (const float*)d_in[0];
    const float* Wt  = (const float*)d_in[1];
    const float* bt  = (const float*)d_in[2];
    const float* Wp  = (const float*)d_in[3];
    const float* bp  = (const float*)d_in[4];
    const float* Wg  = (const float*)d_in[5];
    const float* bg  = (const float*)d_in[6];
    const float* Wo  = (const float*)d_in[7];
    const float* bo  = (const float*)d_in[8];
    const float* gam = (const float*)d_in[9];
    float* out = (float*)d_out;

    pre_kernel<<<BB * MM * 8 / 256, 256>>>(x, Wt, bt, Wp, bp, Wg, bg);

    cudaFuncSetAttribute(attn_kernel,
                         cudaFuncAttributeMaxDynamicSharedMemorySize, SM_ATTN);
    attn_kernel<<<BB * 16, 256, SM_ATTN>>>(x, Wo, bo, gam, out);
}

// round 17
// speedup vs baseline: 1.3970x; 1.3970x over previous
#include <cuda_runtime.h>
#include <cuda_bf16.h>
#include <cstdint>

#define BB 16
#define CC 64
#define NN 4096   // H*W
#define MM 1024   // N/4

// Scratch (allocation-free: __device__ globals)
__device__ __align__(16) float g_theta[BB * NN * 8];              // [b][q][8]
__device__ __align__(16) float g_phi[BB * MM * 8];                // [b][m][8]
__device__ __align__(16) __nv_bfloat16 g_gbf[BB * 32 * MM];       // [b][c'][m] bf16

typedef unsigned long long ull;

__device__ __forceinline__ ull fma2(ull a, ull b, ull c) {
    ull d;
    asm("fma.rn.f32x2 %0, %1, %2, %3;" : "=l"(d) : "l"(a), "l"(b), "l"(c));
    return d;
}
__device__ __forceinline__ ull pack2(float lo, float hi) {
    ull d;
    asm("mov.b64 %0, {%1, %2};" : "=l"(d) : "f"(lo), "f"(hi));
    return d;
}
__device__ __forceinline__ void unpack2(ull v, float& lo, float& hi) {
    asm("mov.b64 {%0, %1}, %2;" : "=f"(lo), "=f"(hi) : "l"(v));
}
__device__ __forceinline__ void u64lohi(ull v, uint32_t& lo, uint32_t& hi) {
    asm("mov.b64 {%0, %1}, %2;" : "=r"(lo), "=r"(hi) : "l"(v));
}
__device__ __forceinline__ uint32_t cvt_tf32(float f) {
    uint32_t r;
    asm("cvt.rna.tf32.f32 %0, %1;" : "=r"(r) : "f"(f));
    return r;
}
__device__ __forceinline__ float ex2f(float x) {
    float r;
    asm("ex2.approx.f32 %0, %1;" : "=f"(r) : "f"(x));
    return r;
}
// returns {lo, hi} packed bf16x2 (PTX: first operand -> high half)
__device__ __forceinline__ uint32_t bf16pk(float hi, float lo) {
    uint32_t r;
    asm("cvt.rn.bf16x2.f32 %0, %1, %2;" : "=r"(r) : "f"(hi), "f"(lo));
    return r;
}
__device__ __forceinline__ void mma_tf32(float& d0, float& d1, float& d2, float& d3,
        uint32_t a0, uint32_t a1, uint32_t a2, uint32_t a3,
        uint32_t b0, uint32_t b1) {
    asm("mma.sync.aligned.m16n8k8.row.col.f32.tf32.tf32.f32 "
        "{%0,%1,%2,%3}, {%4,%5,%6,%7}, {%8,%9}, {%10,%11,%12,%13};"
        : "=f"(d0), "=f"(d1), "=f"(d2), "=f"(d3)
        : "r"(a0), "r"(a1), "r"(a2), "r"(a3), "r"(b0), "r"(b1),
          "f"(0.0f), "f"(0.0f), "f"(0.0f), "f"(0.0f));
}
__device__ __forceinline__ void mma_bf16(float* d,
        uint32_t a0, uint32_t a1, uint32_t a2, uint32_t a3,
        uint32_t b0, uint32_t b1) {
    asm("mma.sync.aligned.m16n8k16.row.col.f32.bf16.bf16.f32 "
        "{%0,%1,%2,%3}, {%4,%5,%6,%7}, {%8,%9}, {%0,%1,%2,%3};"
        : "+f"(d[0]), "+f"(d[1]), "+f"(d[2]), "+f"(d[3])
        : "r"(a0), "r"(a1), "r"(a2), "r"(a3), "r"(b0), "r"(b1));
}

// SMEM layout (attn):
//   phi_p: [1024 rows][32B]  row m, slot t (0-3): u64 {tf32 phi[m][t], tf32 phi[m][t+4]}
//   g_p:   [32 rows][2080B]  pitch ≡32 (mod 128) -> conflict-free LDS.64 phases
#define SO_G      32768
#define G_PITCH   2080
#define G_NT      (8 * G_PITCH)                 // 16640: 8 rows per channel tile
#define SO_WO     (SO_G + 32 * G_PITCH)         // 99328; 64 rows x 72B
#define SO_BIAS   (SO_WO + 64 * 72)             // 103936; 64 floats
#define SM_ATTN   (SO_BIAS + 256)               // 104192

// ---------------------------------------------------------------------------
// Kernel 1: fused theta/phi/g. One thread per (pooled window, position).
//   (R14 version; deeper LDG unroll for MLP)
// ---------------------------------------------------------------------------
__global__ void __launch_bounds__(256) pre_kernel(
        const float* __restrict__ x,
        const float* __restrict__ Wt, const float* __restrict__ bt,
        const float* __restrict__ Wp, const float* __restrict__ bp,
        const float* __restrict__ Wg, const float* __restrict__ bg) {
    __shared__ __align__(16) float WT[64 * 48];  // [c][o]: 0-7 th, 8-15 phi, 16-47 g
    __shared__ float b_s[48];
    int tid = threadIdx.x;
    for (int i = tid; i < 3072; i += 256) {
        int o = i % 48, c = i / 48;
        WT[i] = (o < 8) ? Wt[o * 64 + c]
              : (o < 16) ? Wp[(o - 8) * 64 + c]
                         : Wg[(o - 16) * 64 + c];
    }
    if (tid < 48) b_s[tid] = (tid < 8) ? bt[tid]
                           : (tid < 16) ? bp[tid - 8] : bg[tid - 16];
    __syncthreads();

    int idx = blockIdx.x * 256 + tid;
    int pm = idx >> 2;          // pooled pixel
    int pos = idx & 3;          // window position
    int b = pm >> 10;
    int m = pm & 1023;
    int hp = m >> 5, wp = m & 31;
    int q = (2 * hp + (pos >> 1)) * 64 + 2 * wp + (pos & 1);
    const float* xb = x + (size_t)b * CC * NN + q;

    ull y[24];
    #pragma unroll
    for (int j = 0; j < 24; j++) y[j] = 0ull;
    #pragma unroll 8
    for (int c = 0; c < 64; c++) {
        float xv = xb[(size_t)c * NN];
        ull v2 = pack2(xv, xv);
        const ulonglong2* wr = (const ulonglong2*)(WT + c * 48);
        #pragma unroll
        for (int j = 0; j < 12; j++) {
            ulonglong2 wv = wr[j];
            y[2 * j]     = fma2(v2, wv.x, y[2 * j]);
            y[2 * j + 1] = fma2(v2, wv.y, y[2 * j + 1]);
        }
    }
    float v[48];
    #pragma unroll
    for (int j = 0; j < 24; j++) unpack2(y[j], v[2 * j], v[2 * j + 1]);

    // theta: every thread stores its own pixel
    {
        float4* op = (float4*)(g_theta + ((size_t)b * NN + q) * 8);
        op[0] = make_float4(v[0] + b_s[0], v[1] + b_s[1],
                            v[2] + b_s[2], v[3] + b_s[3]);
        op[1] = make_float4(v[4] + b_s[4], v[5] + b_s[5],
                            v[6] + b_s[6], v[7] + b_s[7]);
    }
    // phi/g: maxpool across the quad
    #pragma unroll
    for (int j = 8; j < 48; j++) {
        v[j] = fmaxf(v[j], __shfl_xor_sync(0xffffffffu, v[j], 1));
        v[j] = fmaxf(v[j], __shfl_xor_sync(0xffffffffu, v[j], 2));
    }
    if (pos == 0) {
        float* php = g_phi + (size_t)pm * 8;
        #pragma unroll
        for (int k = 0; k < 8; k++) php[k] = v[8 + k] + b_s[8 + k];
        __nv_bfloat16* gp = g_gbf + (size_t)b * 32 * MM + m;
        #pragma unroll
        for (int j = 0; j < 32; j++)
            gp[(size_t)j * MM] = __float2bfloat16(v[16 + j] + b_s[16 + j]);
    }
}

// ---------------------------------------------------------------------------
// Kernel 2: fused flash attention + output projection + residual.
//   Two 16-query groups per warp share key-chunk B fragments. Denominator
//   computed by an extra mma against a constant ones-column B fragment
//   (no LDS, no FADD chain): denom accumulates in D-frag col 0.
// ---------------------------------------------------------------------------
__global__ void __launch_bounds__(256, 2) attn_kernel(
        const float* __restrict__ x,
        const float* __restrict__ Wo, const float* __restrict__ bo,
        const float* __restrict__ gam,
        float* __restrict__ out) {
    extern __shared__ __align__(16) char sm[];
    char* wo_s = sm + SO_WO;                   // 64 rows x 72B (bf16 pairs)
    float* b_s = (float*)(sm + SO_BIAS);       // 64 floats

    int tid = threadIdx.x;
    int b = blockIdx.x >> 4;
    int qt = blockIdx.x & 15;

    // Stage phi (packed tf32 pairs), g (packed bf16 u64 slots), W_o, bias
    {
        for (int m = tid; m < 1024; m += 256) {
            const float4* pr = (const float4*)(g_phi + ((size_t)b * MM + m) * 8);
            float4 f0 = pr[0], f1 = pr[1];
            uint2* dst = (uint2*)(sm + m * 32);
            dst[0] = make_uint2(cvt_tf32(f0.x), cvt_tf32(f1.x));
            dst[1] = make_uint2(cvt_tf32(f0.y), cvt_tf32(f1.y));
            dst[2] = make_uint2(cvt_tf32(f0.z), cvt_tf32(f1.z));
            dst[3] = make_uint2(cvt_tf32(f0.w), cvt_tf32(f1.w));
        }
        const uint32_t* gsrc = (const uint32_t*)(g_gbf + (size_t)b * 32 * MM);
        for (int i = tid; i < 8192; i += 256) {
            int r = i >> 8;            // 0..31
            int c = (i >> 2) & 63;     // chunk
            int t = i & 3;             // slot
            const uint32_t* src = gsrc + r * (MM / 2) + c * 8;
            *(uint2*)(sm + SO_G + r * G_PITCH + c * 32 + t * 8) =
                make_uint2(src[t], src[t + 4]);
        }
        for (int i = tid; i < 1024; i += 256) {        // W_o: [co][ci pair]
            int co = i >> 4, pr = i & 15;
            float lo = Wo[co * 32 + 2 * pr];
            float hi = Wo[co * 32 + 2 * pr + 1];
            *(uint32_t*)(wo_s + co * 72 + pr * 4) = bf16pk(hi, lo);
        }
        if (tid < 64) b_s[tid] = bo[tid];
    }
    __syncthreads();

    int w = tid >> 5, lane = tid & 31;
    int t4 = lane >> 2, tm4 = lane & 3;
    int q0 = qt * 256 + w * 16;            // group A queries
    int q1 = q0 + 128;                     // group B queries

    // B fragment of the ones-column matrix (col n=0 all ones): n index = t4
    uint32_t oneB = (t4 == 0) ? 0x3F803F80u : 0u;

    // theta A-fragments (tf32), pre-scaled by log2(e)
    const float L2E = 1.4426950408889634f;
    const float* tpA = g_theta + ((size_t)b * NN + q0) * 8;
    const float* tpB = g_theta + ((size_t)b * NN + q1) * 8;
    uint32_t taA0 = cvt_tf32(tpA[t4 * 8 + tm4] * L2E);
    uint32_t taA1 = cvt_tf32(tpA[(t4 + 8) * 8 + tm4] * L2E);
    uint32_t taA2 = cvt_tf32(tpA[t4 * 8 + tm4 + 4] * L2E);
    uint32_t taA3 = cvt_tf32(tpA[(t4 + 8) * 8 + tm4 + 4] * L2E);
    uint32_t taB0 = cvt_tf32(tpB[t4 * 8 + tm4] * L2E);
    uint32_t taB1 = cvt_tf32(tpB[(t4 + 8) * 8 + tm4] * L2E);
    uint32_t taB2 = cvt_tf32(tpB[t4 * 8 + tm4 + 4] * L2E);
    uint32_t taB3 = cvt_tf32(tpB[(t4 + 8) * 8 + tm4 + 4] * L2E);

    float oA[16], oB[16];
    #pragma unroll
    for (int j = 0; j < 16; j++) { oA[j] = 0.0f; oB[j] = 0.0f; }
    float dA[4] = {0.0f, 0.0f, 0.0f, 0.0f};
    float dB[4] = {0.0f, 0.0f, 0.0f, 0.0f};

    const char* pp = sm + t4 * 32 + tm4 * 8;                 // phi ptr, +512/chunk
    const char* gp = sm + SO_G + t4 * G_PITCH + tm4 * 8;     // g ptr,  +32/chunk

    #pragma unroll 2
    for (int ch = 0; ch < 64; ch++) {
        // B fragments: 6x LDS.64, zero address math
        ull vpb = *(const ull*)pp;
        ull vpc = *(const ull*)(pp + 256);
        ull vg0 = *(const ull*)gp;
        ull vg1 = *(const ull*)(gp + G_NT);
        ull vg2 = *(const ull*)(gp + 2 * G_NT);
        ull vg3 = *(const ull*)(gp + 3 * G_NT);
        pp += 512;
        gp += 32;

        uint32_t pb0, pb1, pc0, pc1;
        u64lohi(vpb, pb0, pb1);
        u64lohi(vpc, pc0, pc1);
        uint32_t gb0[4], gb1[4];
        u64lohi(vg0, gb0[0], gb1[0]);
        u64lohi(vg1, gb0[1], gb1[1]);
        u64lohi(vg2, gb0[2], gb1[2]);
        u64lohi(vg3, gb0[3], gb1[3]);

        // ---- group A ----
        float s0, s1, s2, s3, s4, s5, s6, s7;
        mma_tf32(s0, s1, s2, s3, taA0, taA1, taA2, taA3, pb0, pb1);
        mma_tf32(s4, s5, s6, s7, taA0, taA1, taA2, taA3, pc0, pc1);
        float a0 = ex2f(s0), a1 = ex2f(s1), a2 = ex2f(s2), a3 = ex2f(s3);
        float a4 = ex2f(s4), a5 = ex2f(s5), a6 = ex2f(s6), a7 = ex2f(s7);
        uint32_t paA0 = bf16pk(a1, a0);
        uint32_t paA1 = bf16pk(a3, a2);
        uint32_t paA2 = bf16pk(a5, a4);
        uint32_t paA3 = bf16pk(a7, a6);

        // ---- group B ----
        float u0, u1, u2, u3, u4, u5, u6, u7;
        mma_tf32(u0, u1, u2, u3, taB0, taB1, taB2, taB3, pb0, pb1);
        mma_tf32(u4, u5, u6, u7, taB0, taB1, taB2, taB3, pc0, pc1);
        float c0 = ex2f(u0), c1 = ex2f(u1), c2 = ex2f(u2), c3 = ex2f(u3);
        float c4 = ex2f(u4), c5 = ex2f(u5), c6 = ex2f(u6), c7 = ex2f(u7);
        uint32_t paB0 = bf16pk(c1, c0);
        uint32_t paB1 = bf16pk(c3, c2);
        uint32_t paB2 = bf16pk(c5, c4);
        uint32_t paB3 = bf16pk(c7, c6);

        // O += P @ g^T (4 tiles) and denom += P @ ones (free B frag)
        #pragma unroll
        for (int nt = 0; nt < 4; nt++) {
            mma_bf16(oA + nt * 4, paA0, paA1, paA2, paA3, gb0[nt], gb1[nt]);
            mma_bf16(oB + nt * 4, paB0, paB1, paB2, paB3, gb0[nt], gb1[nt]);
        }
        mma_bf16(dA, paA0, paA1, paA2, paA3, oneB, oneB);
        mma_bf16(dB, paB0, paB1, paB2, paB3, oneB, oneB);
    }

    // denom lives in threads tm4==0: dX[0] = row t4, dX[2] = row t4+8.
    // Broadcast within each quad (src lane = lane & ~3).
    int src = lane & 28;
    float denA_lo = __shfl_sync(0xffffffffu, dA[0], src);
    float denA_hi = __shfl_sync(0xffffffffu, dA[2], src);
    float denB_lo = __shfl_sync(0xffffffffu, dB[0], src);
    float denB_hi = __shfl_sync(0xffffffffu, dB[2], src);
    float ilA = 1.0f / denA_lo, ihA = 1.0f / denA_hi;
    float ilB = 1.0f / denB_lo, ihB = 1.0f / denB_hi;

    // ---- fused output projection + residual, both groups ----
    uint32_t paA[8], paB[8];
    #pragma unroll
    for (int h = 0; h < 4; h++) {
        paA[2 * h]     = bf16pk(oA[4 * h + 1] * ilA, oA[4 * h]     * ilA);
        paA[2 * h + 1] = bf16pk(oA[4 * h + 3] * ihA, oA[4 * h + 2] * ihA);
        paB[2 * h]     = bf16pk(oB[4 * h + 1] * ilB, oB[4 * h]     * ilB);
        paB[2 * h + 1] = bf16pk(oB[4 * h + 3] * ihB, oB[4 * h + 2] * ihB);
    }

    float gma = gam[0];
    const float* xb = x + (size_t)b * CC * NN;
    float* outb = out + (size_t)b * CC * NN;
    int qA_lo = q0 + t4, qA_hi = qA_lo + 8;
    int qB_lo = q1 + t4, qB_hi = qB_lo + 8;

    #pragma unroll
    for (int ntc = 0; ntc < 8; ntc++) {
        const char* wb = wo_s + (ntc * 8 + t4) * 72 + tm4 * 4;
        uint32_t w0 = *(const uint32_t*)wb;
        uint32_t w1 = *(const uint32_t*)(wb + 16);
        uint32_t w2 = *(const uint32_t*)(wb + 32);
        uint32_t w3 = *(const uint32_t*)(wb + 48);
        int co = ntc * 8 + 2 * tm4;
        size_t r0 = (size_t)co * NN, r1 = (size_t)(co + 1) * NN;
        float bc0 = b_s[co], bc1 = b_s[co + 1];

        float accA[4] = {0.0f, 0.0f, 0.0f, 0.0f};
        mma_bf16(accA, paA[0], paA[1], paA[2], paA[3], w0, w1);
        mma_bf16(accA, paA[4], paA[5], paA[6], paA[7], w2, w3);
        outb[r0 + qA_lo] = gma * (accA[0] + bc0) + xb[r0 + qA_lo];
        outb[r1 + qA_lo] = gma * (accA[1] + bc1) + xb[r1 + qA_lo];
        outb[r0 + qA_hi] = gma * (accA[2] + bc0) + xb[r0 + qA_hi];
        outb[r1 + qA_hi] = gma * (accA[3] + bc1) + xb[r1 + qA_hi];

        float accB[4] = {0.0f, 0.0f, 0.0f, 0.0f};
        mma_bf16(accB, paB[0], paB[1], paB[2], paB[3], w0, w1);
        mma_bf16(accB, paB[4], paB[5], paB[6], paB[7], w2, w3);
        outb[r0 + qB_lo] = gma * (accB[0] + bc0) + xb[r0 + qB_lo];
        outb[r1 + qB_lo] = gma * (accB[1] + bc1) + xb[r1 + qB_lo];
        outb[r0 + qB_hi] = gma * (accB[2] + bc0) + xb[r0 + qB_hi];
        outb[r1 + qB_hi] = gma * (accB[3] + bc1) + xb[r1 + qB_hi];
    }
}

// ---------------------------------------------------------------------------
extern "C" void kernel_launch(void* const* d_in, const int* in_sizes, int n_in,
                              void* d_out, int out_size) {
    const float* x   = (const float*)d_in[0];
    const float* Wt  = (const float*)d_in[1];
    const float* bt  = (const float*)d_in[2];
    const float* Wp  = (const float*)d_in[3];
    const float* bp  = (const float*)d_in[4];
    const float* Wg  = (const float*)d_in[5];
    const float* bg  = (const float*)d_in[6];
    const float* Wo  = (const float*)d_in[7];
    const float* bo  = (const float*)d_in[8];
    const float* gam = (const float*)d_in[9];
    float* out = (float*)d_out;

    pre_kernel<<<BB * MM * 4 / 256, 256>>>(x, Wt, bt, Wp, bp, Wg, bg);

    cudaFuncSetAttribute(attn_kernel,
                         cudaFuncAttributeMaxDynamicSharedMemorySize, SM_ATTN);
    attn_kernel<<<BB * 16, 256, SM_ATTN>>>(x, Wo, bo, gam, out);
}